// round 1
// baseline (speedup 1.0000x reference)
#include <cuda_runtime.h>

// Problem constants
#define NPTS 100000
#define CIN  16
#define FOUT 16
#define BW   8
#define NDIM 3
#define NSEG 8192

// Tiling for the pre-conv kernel
#define PN   128                      // points per CTA
#define T1   256                      // threads per CTA
#define XROWS ((PN + 2) * (BW + 2))   // 130 * 10 = 1300 rows (point-halo + w-pad)
#define XSTR  17                      // channel stride (conflict-free LDS)
#define SM_FLOATS (XROWS * XSTR + 2304 + 16)
#define SM_BYTES  (SM_FLOATS * 4)

// Device scratch (static allocation — no cudaMalloc allowed)
__device__ float g_seg[NDIM * NSEG * BW * FOUT];   // segment sums, 12.6 MB
__device__ float g_z  [NDIM * NSEG * BW * FOUT];   // post-conv output, 12.6 MB

// Packed fp32x2 FMA (Blackwell FFMA2 — PTX-only)
#define FMA2(acc, x2, w2) \
    asm("fma.rn.f32x2 %0, %1, %2, %0;" : "+l"(acc) : "l"(x2), "l"(w2))
#define PACK2(dst, f) \
    asm("mov.b64 %0, {%1, %2};" : "=l"(dst) : "f"(f), "f"(f))

// ---------------------------------------------------------------------------
// Kernel 0: zero the segment-sum scratch (must run every launch / graph replay)
// ---------------------------------------------------------------------------
__global__ void zero_seg_kernel() {
    const int total = NDIM * NSEG * BW * FOUT / 4;
    float4* p = reinterpret_cast<float4*>(g_seg);
    const float4 z = make_float4(0.f, 0.f, 0.f, 0.f);
    for (int i = blockIdx.x * blockDim.x + threadIdx.x; i < total;
         i += gridDim.x * blockDim.x)
        p[i] = z;
}

// ---------------------------------------------------------------------------
// Kernel 1: gather X[inv] -> 3x3 conv + relu -> atomic segment-sum
// grid: (ceil(N/PN), NDIM), block: 256
// smem: xs[(PN+2)*(BW+2)][17] zero-padded image tile, ws[3*3*16*16], bs[16]
// Each thread computes 4 (point, w) pairs for all 16 filters via FFMA2.
// ---------------------------------------------------------------------------
__global__ void __launch_bounds__(T1, 2)
pre_conv_kernel(const float* __restrict__ X, const int* __restrict__ inv,
                const int* __restrict__ index,
                const float* __restrict__ pre_w, const float* __restrict__ pre_b)
{
    extern __shared__ float sm[];
    float* xs = sm;                       // XROWS * XSTR
    float* ws = sm + XROWS * XSTR;        // 2304 = 3*3*16*16
    float* bs = ws + 2304;                // 16

    const int tid    = threadIdx.x;
    const int d      = blockIdx.y;
    const int bstart = blockIdx.x * PN;

    // Load weights + bias for this dim
    for (int i = tid; i < 2304; i += T1) ws[i] = pre_w[d * 2304 + i];
    if (tid < FOUT) bs[tid] = pre_b[d * FOUT + tid];

    // Gather phase: rows are (point-with-halo, w-with-pad); edges stay zero.
    for (int r = tid; r < XROWS; r += T1) {
        const int pt = r / (BW + 2);
        const int wc = r - pt * (BW + 2);     // 0..9, slot 0 and 9 = w padding
        const int gp = bstart - 1 + pt;       // global point, -1 halo
        float4 v0 = make_float4(0.f, 0.f, 0.f, 0.f), v1 = v0, v2 = v0, v3 = v0;
        if (wc >= 1 && wc <= BW && gp >= 0 && gp < NPTS) {
            const int idx = inv[(d * NPTS + gp) * BW + (wc - 1)];
            const float4* xp = reinterpret_cast<const float4*>(X) + idx * 4;
            v0 = xp[0]; v1 = xp[1]; v2 = xp[2]; v3 = xp[3];
        }
        float* dst = xs + r * XSTR;
        dst[0] = v0.x;  dst[1] = v0.y;  dst[2]  = v0.z;  dst[3]  = v0.w;
        dst[4] = v1.x;  dst[5] = v1.y;  dst[6]  = v1.z;  dst[7]  = v1.w;
        dst[8] = v2.x;  dst[9] = v2.y;  dst[10] = v2.z;  dst[11] = v2.w;
        dst[12] = v3.x; dst[13] = v3.y; dst[14] = v3.z;  dst[15] = v3.w;
    }
    __syncthreads();

    const int w  = tid & 7;      // beam position
    const int p0 = tid >> 3;     // local point 0..31 (pairs j add 32 each)

    // 4 pairs x 16 filters as 8 packed f32x2 accumulators each
    unsigned long long acc[4][8];
#pragma unroll
    for (int j = 0; j < 4; ++j)
#pragma unroll
        for (int q = 0; q < 8; ++q) acc[j][q] = 0ull;

    const int JSTR = 32 * (BW + 2) * XSTR;   // 5440 floats between j-pairs

#pragma unroll 1
    for (int a = 0; a < 3; ++a) {
#pragma unroll 1
        for (int b = 0; b < 3; ++b) {
            // input point = p + a - 1 -> smem point row p + a (halo offset)
            // input w     = w + b - 1 -> smem w slot  w + b (pad offset)
            const float* xb = xs + ((p0 + a) * (BW + 2) + (w + b)) * XSTR;
            const ulonglong2* wb =
                reinterpret_cast<const ulonglong2*>(ws + (a * 3 + b) * 256);
#pragma unroll
            for (int c = 0; c < CIN; ++c) {
                const float x0 = xb[c];
                const float x1 = xb[c + JSTR];
                const float x2 = xb[c + 2 * JSTR];
                const float x3 = xb[c + 3 * JSTR];
                unsigned long long x20, x21, x22, x23;
                PACK2(x20, x0); PACK2(x21, x1); PACK2(x22, x2); PACK2(x23, x3);
                const ulonglong2 wA = wb[c * 4 + 0];   // filters 0..3
                const ulonglong2 wB = wb[c * 4 + 1];   // filters 4..7
                const ulonglong2 wC = wb[c * 4 + 2];   // filters 8..11
                const ulonglong2 wD = wb[c * 4 + 3];   // filters 12..15
                FMA2(acc[0][0], x20, wA.x); FMA2(acc[0][1], x20, wA.y);
                FMA2(acc[0][2], x20, wB.x); FMA2(acc[0][3], x20, wB.y);
                FMA2(acc[0][4], x20, wC.x); FMA2(acc[0][5], x20, wC.y);
                FMA2(acc[0][6], x20, wD.x); FMA2(acc[0][7], x20, wD.y);
                FMA2(acc[1][0], x21, wA.x); FMA2(acc[1][1], x21, wA.y);
                FMA2(acc[1][2], x21, wB.x); FMA2(acc[1][3], x21, wB.y);
                FMA2(acc[1][4], x21, wC.x); FMA2(acc[1][5], x21, wC.y);
                FMA2(acc[1][6], x21, wD.x); FMA2(acc[1][7], x21, wD.y);
                FMA2(acc[2][0], x22, wA.x); FMA2(acc[2][1], x22, wA.y);
                FMA2(acc[2][2], x22, wB.x); FMA2(acc[2][3], x22, wB.y);
                FMA2(acc[2][4], x22, wC.x); FMA2(acc[2][5], x22, wC.y);
                FMA2(acc[2][6], x22, wD.x); FMA2(acc[2][7], x22, wD.y);
                FMA2(acc[3][0], x23, wA.x); FMA2(acc[3][1], x23, wA.y);
                FMA2(acc[3][2], x23, wB.x); FMA2(acc[3][3], x23, wB.y);
                FMA2(acc[3][4], x23, wC.x); FMA2(acc[3][5], x23, wC.y);
                FMA2(acc[3][6], x23, wD.x); FMA2(acc[3][7], x23, wD.y);
            }
        }
    }

    // Epilogue: bias + relu + vectorized atomic segment sum
#pragma unroll
    for (int j = 0; j < 4; ++j) {
        const int gp = bstart + p0 + j * 32;
        if (gp >= NPTS) continue;
        const int seg = index[d * NPTS + gp];
        float* dstp = g_seg + ((d * NSEG + seg) * BW + w) * FOUT;
        float fv[16];
#pragma unroll
        for (int q = 0; q < 8; ++q) {
            float lo, hi;
            asm("mov.b64 {%0, %1}, %2;" : "=f"(lo), "=f"(hi) : "l"(acc[j][q]));
            fv[2 * q] = lo; fv[2 * q + 1] = hi;
        }
#pragma unroll
        for (int fg = 0; fg < 4; ++fg) {
            const float v0 = fmaxf(fv[fg * 4 + 0] + bs[fg * 4 + 0], 0.f);
            const float v1 = fmaxf(fv[fg * 4 + 1] + bs[fg * 4 + 1], 0.f);
            const float v2 = fmaxf(fv[fg * 4 + 2] + bs[fg * 4 + 2], 0.f);
            const float v3 = fmaxf(fv[fg * 4 + 3] + bs[fg * 4 + 3], 0.f);
            asm volatile("red.global.add.v4.f32 [%0], {%1,%2,%3,%4};"
                         :: "l"(dstp + fg * 4),
                            "f"(v0), "f"(v1), "f"(v2), "f"(v3)
                         : "memory");
        }
    }
}

// ---------------------------------------------------------------------------
// Kernel 2: post conv (3,1) + relu on g_seg -> g_z
// grid: (NSEG*BW/256, NDIM), block 256; one thread per (segment, w)
// ---------------------------------------------------------------------------
__global__ void __launch_bounds__(256)
post_conv_kernel(const float* __restrict__ post_w, const float* __restrict__ post_b)
{
    __shared__ float ws[768];   // [a][c][f] = 3*16*16
    __shared__ float bs[16];
    const int tid = threadIdx.x;
    const int d   = blockIdx.y;
    for (int i = tid; i < 768; i += 256) ws[i] = post_w[d * 768 + i];
    if (tid < FOUT) bs[tid] = post_b[d * FOUT + tid];
    __syncthreads();

    const int gt = blockIdx.x * 256 + tid;    // 0 .. NSEG*BW-1
    const int s  = gt >> 3;
    const int w  = gt & 7;

    float acc[16];
#pragma unroll
    for (int f = 0; f < 16; ++f) acc[f] = 0.f;

#pragma unroll
    for (int a = 0; a < 3; ++a) {
        const int ss = s + a - 1;
        if (ss < 0 || ss >= NSEG) continue;
        const float4* src = reinterpret_cast<const float4*>(
            g_seg + ((d * NSEG + ss) * BW + w) * FOUT);
#pragma unroll
        for (int cg = 0; cg < 4; ++cg) {
            const float4 x4 = src[cg];
            const float* wr = ws + (a * 16 + cg * 4) * 16;
#pragma unroll
            for (int f = 0; f < 16; ++f) acc[f] += x4.x * wr[f];
#pragma unroll
            for (int f = 0; f < 16; ++f) acc[f] += x4.y * wr[16 + f];
#pragma unroll
            for (int f = 0; f < 16; ++f) acc[f] += x4.z * wr[32 + f];
#pragma unroll
            for (int f = 0; f < 16; ++f) acc[f] += x4.w * wr[48 + f];
        }
    }

    float4* dst = reinterpret_cast<float4*>(g_z + ((d * NSEG + s) * BW + w) * FOUT);
#pragma unroll
    for (int fg = 0; fg < 4; ++fg) {
        float4 v;
        v.x = fmaxf(acc[fg * 4 + 0] + bs[fg * 4 + 0], 0.f);
        v.y = fmaxf(acc[fg * 4 + 1] + bs[fg * 4 + 1], 0.f);
        v.z = fmaxf(acc[fg * 4 + 2] + bs[fg * 4 + 2], 0.f);
        v.w = fmaxf(acc[fg * 4 + 3] + bs[fg * 4 + 3], 0.f);
        dst[fg] = v;
    }
}

// ---------------------------------------------------------------------------
// Kernel 3: Y[n,w,:] = sum_d g_z[d, index[d,n], w, :]
// one thread per (n, w) row of 16 floats
// ---------------------------------------------------------------------------
__global__ void __launch_bounds__(256)
gather_out_kernel(const int* __restrict__ index, float* __restrict__ out)
{
    const int gt = blockIdx.x * 256 + threadIdx.x;
    if (gt >= NPTS * BW) return;
    const int n = gt >> 3;
    const int w = gt & 7;

    float4 a0 = make_float4(0.f, 0.f, 0.f, 0.f), a1 = a0, a2 = a0, a3 = a0;
#pragma unroll
    for (int d = 0; d < NDIM; ++d) {
        const int s = index[d * NPTS + n];
        const float4* src = reinterpret_cast<const float4*>(
            g_z + ((d * NSEG + s) * BW + w) * FOUT);
        const float4 b0 = src[0], b1 = src[1], b2 = src[2], b3 = src[3];
        a0.x += b0.x; a0.y += b0.y; a0.z += b0.z; a0.w += b0.w;
        a1.x += b1.x; a1.y += b1.y; a1.z += b1.z; a1.w += b1.w;
        a2.x += b2.x; a2.y += b2.y; a2.z += b2.z; a2.w += b2.w;
        a3.x += b3.x; a3.y += b3.y; a3.z += b3.z; a3.w += b3.w;
    }
    float4* dst = reinterpret_cast<float4*>(out + gt * FOUT);
    dst[0] = a0; dst[1] = a1; dst[2] = a2; dst[3] = a3;
}

// ---------------------------------------------------------------------------
extern "C" void kernel_launch(void* const* d_in, const int* in_sizes, int n_in,
                              void* d_out, int out_size)
{
    const float* X      = (const float*)d_in[0];
    const int*   inv    = (const int*)  d_in[1];
    const int*   index  = (const int*)  d_in[2];
    const float* pre_w  = (const float*)d_in[3];
    const float* pre_b  = (const float*)d_in[4];
    const float* post_w = (const float*)d_in[5];
    const float* post_b = (const float*)d_in[6];
    float*       out    = (float*)      d_out;

    cudaFuncSetAttribute((const void*)pre_conv_kernel,
                         cudaFuncAttributeMaxDynamicSharedMemorySize, SM_BYTES);

    zero_seg_kernel<<<1024, 256>>>();

    dim3 g1((NPTS + PN - 1) / PN, NDIM);
    pre_conv_kernel<<<g1, T1, SM_BYTES>>>(X, inv, index, pre_w, pre_b);

    dim3 g2(NSEG * BW / 256, NDIM);
    post_conv_kernel<<<g2, 256>>>(post_w, post_b);

    gather_out_kernel<<<(NPTS * BW + 255) / 256, 256>>>(index, out);
}

// round 2
// speedup vs baseline: 1.0156x; 1.0156x over previous
#include <cuda_runtime.h>

// Problem constants
#define NPTS 100000
#define CIN  16
#define FOUT 16
#define BW   8
#define NDIM 3
#define NSEG 8192

// Tiling for the pre-conv kernel (PN=64 -> 54KB smem -> 3 CTAs/SM)
#define PN   64                       // points per CTA
#define T1   256                      // threads per CTA
#define XROWS ((PN + 2) * (BW + 2))   // 66 * 10 = 660 rows (point-halo + w-pad)
#define XSTR  17                      // channel stride (conflict-free LDS)
#define SM_FLOATS (XROWS * XSTR + 2304 + 16)
#define SM_BYTES  (SM_FLOATS * 4)

// Device scratch (static allocation — no cudaMalloc allowed)
__device__ float g_seg[NDIM * NSEG * BW * FOUT];   // segment sums, 12.6 MB
__device__ float g_z  [NDIM * NSEG * BW * FOUT];   // post-conv output, 12.6 MB

// Packed fp32x2 FMA (Blackwell FFMA2 — PTX-only)
#define FMA2(acc, x2, w2) \
    asm("fma.rn.f32x2 %0, %1, %2, %0;" : "+l"(acc) : "l"(x2), "l"(w2))
#define PACK2(dst, f) \
    asm("mov.b64 %0, {%1, %2};" : "=l"(dst) : "f"(f), "f"(f))

// ---------------------------------------------------------------------------
// Kernel 0: zero the segment-sum scratch (must run every launch / graph replay)
// ---------------------------------------------------------------------------
__global__ void zero_seg_kernel() {
    const int total = NDIM * NSEG * BW * FOUT / 4;
    float4* p = reinterpret_cast<float4*>(g_seg);
    const float4 z = make_float4(0.f, 0.f, 0.f, 0.f);
    for (int i = blockIdx.x * blockDim.x + threadIdx.x; i < total;
         i += gridDim.x * blockDim.x)
        p[i] = z;
}

// ---------------------------------------------------------------------------
// Kernel 1: gather X[inv] -> 3x3 conv + relu -> atomic segment-sum
// grid: (ceil(N/PN), NDIM), block: 256, 3 CTAs/SM
// smem: xs[(PN+2)*(BW+2)][17] zero-padded image tile, ws[3*3*16*16], bs[16]
// Each thread computes 2 (point, w) pairs for all 16 filters via FFMA2.
// ---------------------------------------------------------------------------
__global__ void __launch_bounds__(T1, 3)
pre_conv_kernel(const float* __restrict__ X, const int* __restrict__ inv,
                const int* __restrict__ index,
                const float* __restrict__ pre_w, const float* __restrict__ pre_b)
{
    extern __shared__ float sm[];
    float* xs = sm;                       // XROWS * XSTR
    float* ws = sm + XROWS * XSTR;        // 2304 = 3*3*16*16
    float* bs = ws + 2304;                // 16

    const int tid    = threadIdx.x;
    const int d      = blockIdx.y;
    const int bstart = blockIdx.x * PN;

    // Load weights + bias for this dim
    for (int i = tid; i < 2304; i += T1) ws[i] = pre_w[d * 2304 + i];
    if (tid < FOUT) bs[tid] = pre_b[d * FOUT + tid];

    // Gather phase: rows are (point-with-halo, w-with-pad); edges stay zero.
    for (int r = tid; r < XROWS; r += T1) {
        const int pt = r / (BW + 2);
        const int wc = r - pt * (BW + 2);     // 0..9, slot 0 and 9 = w padding
        const int gp = bstart - 1 + pt;       // global point, -1 halo
        float4 v0 = make_float4(0.f, 0.f, 0.f, 0.f), v1 = v0, v2 = v0, v3 = v0;
        if (wc >= 1 && wc <= BW && gp >= 0 && gp < NPTS) {
            const int idx = inv[(d * NPTS + gp) * BW + (wc - 1)];
            const float4* xp = reinterpret_cast<const float4*>(X) + idx * 4;
            v0 = xp[0]; v1 = xp[1]; v2 = xp[2]; v3 = xp[3];
        }
        float* dst = xs + r * XSTR;
        dst[0] = v0.x;  dst[1] = v0.y;  dst[2]  = v0.z;  dst[3]  = v0.w;
        dst[4] = v1.x;  dst[5] = v1.y;  dst[6]  = v1.z;  dst[7]  = v1.w;
        dst[8] = v2.x;  dst[9] = v2.y;  dst[10] = v2.z;  dst[11] = v2.w;
        dst[12] = v3.x; dst[13] = v3.y; dst[14] = v3.z;  dst[15] = v3.w;
    }
    __syncthreads();

    const int w  = tid & 7;      // beam position
    const int p0 = tid >> 3;     // local point 0..31 (pair j adds 32)

    // 2 pairs x 16 filters as 8 packed f32x2 accumulators each
    unsigned long long acc[2][8];
#pragma unroll
    for (int j = 0; j < 2; ++j)
#pragma unroll
        for (int q = 0; q < 8; ++q) acc[j][q] = 0ull;

    const int JSTR = 32 * (BW + 2) * XSTR;   // 5440 floats between j-pairs

#pragma unroll 1
    for (int a = 0; a < 3; ++a) {
#pragma unroll 1
        for (int b = 0; b < 3; ++b) {
            const float* xb = xs + ((p0 + a) * (BW + 2) + (w + b)) * XSTR;
            const ulonglong2* wb =
                reinterpret_cast<const ulonglong2*>(ws + (a * 3 + b) * 256);
#pragma unroll
            for (int c = 0; c < CIN; ++c) {
                const float x0 = xb[c];
                const float x1 = xb[c + JSTR];
                unsigned long long x20, x21;
                PACK2(x20, x0); PACK2(x21, x1);
                const ulonglong2 wA = wb[c * 4 + 0];   // filters 0..3
                const ulonglong2 wB = wb[c * 4 + 1];   // filters 4..7
                const ulonglong2 wC = wb[c * 4 + 2];   // filters 8..11
                const ulonglong2 wD = wb[c * 4 + 3];   // filters 12..15
                FMA2(acc[0][0], x20, wA.x); FMA2(acc[0][1], x20, wA.y);
                FMA2(acc[0][2], x20, wB.x); FMA2(acc[0][3], x20, wB.y);
                FMA2(acc[0][4], x20, wC.x); FMA2(acc[0][5], x20, wC.y);
                FMA2(acc[0][6], x20, wD.x); FMA2(acc[0][7], x20, wD.y);
                FMA2(acc[1][0], x21, wA.x); FMA2(acc[1][1], x21, wA.y);
                FMA2(acc[1][2], x21, wB.x); FMA2(acc[1][3], x21, wB.y);
                FMA2(acc[1][4], x21, wC.x); FMA2(acc[1][5], x21, wC.y);
                FMA2(acc[1][6], x21, wD.x); FMA2(acc[1][7], x21, wD.y);
            }
        }
    }

    // Epilogue: bias + relu + vectorized atomic segment sum
#pragma unroll
    for (int j = 0; j < 2; ++j) {
        const int gp = bstart + p0 + j * 32;
        if (gp >= NPTS) continue;
        const int seg = index[d * NPTS + gp];
        float* dstp = g_seg + ((d * NSEG + seg) * BW + w) * FOUT;
        float fv[16];
#pragma unroll
        for (int q = 0; q < 8; ++q) {
            float lo, hi;
            asm("mov.b64 {%0, %1}, %2;" : "=f"(lo), "=f"(hi) : "l"(acc[j][q]));
            fv[2 * q] = lo; fv[2 * q + 1] = hi;
        }
#pragma unroll
        for (int fg = 0; fg < 4; ++fg) {
            const float v0 = fmaxf(fv[fg * 4 + 0] + bs[fg * 4 + 0], 0.f);
            const float v1 = fmaxf(fv[fg * 4 + 1] + bs[fg * 4 + 1], 0.f);
            const float v2 = fmaxf(fv[fg * 4 + 2] + bs[fg * 4 + 2], 0.f);
            const float v3 = fmaxf(fv[fg * 4 + 3] + bs[fg * 4 + 3], 0.f);
            asm volatile("red.global.add.v4.f32 [%0], {%1,%2,%3,%4};"
                         :: "l"(dstp + fg * 4),
                            "f"(v0), "f"(v1), "f"(v2), "f"(v3)
                         : "memory");
        }
    }
}

// ---------------------------------------------------------------------------
// Kernel 2: post conv (3,1) + relu on g_seg -> g_z
// grid: (NSEG*BW/256, NDIM), block 256; one thread per (segment, w)
// ---------------------------------------------------------------------------
__global__ void __launch_bounds__(256)
post_conv_kernel(const float* __restrict__ post_w, const float* __restrict__ post_b)
{
    __shared__ float ws[768];   // [a][c][f] = 3*16*16
    __shared__ float bs[16];
    const int tid = threadIdx.x;
    const int d   = blockIdx.y;
    for (int i = tid; i < 768; i += 256) ws[i] = post_w[d * 768 + i];
    if (tid < FOUT) bs[tid] = post_b[d * FOUT + tid];
    __syncthreads();

    const int gt = blockIdx.x * 256 + tid;    // 0 .. NSEG*BW-1
    const int s  = gt >> 3;
    const int w  = gt & 7;

    float acc[16];
#pragma unroll
    for (int f = 0; f < 16; ++f) acc[f] = 0.f;

#pragma unroll
    for (int a = 0; a < 3; ++a) {
        const int ss = s + a - 1;
        if (ss < 0 || ss >= NSEG) continue;
        const float4* src = reinterpret_cast<const float4*>(
            g_seg + ((d * NSEG + ss) * BW + w) * FOUT);
#pragma unroll
        for (int cg = 0; cg < 4; ++cg) {
            const float4 x4 = src[cg];
            const float* wr = ws + (a * 16 + cg * 4) * 16;
#pragma unroll
            for (int f = 0; f < 16; ++f) acc[f] += x4.x * wr[f];
#pragma unroll
            for (int f = 0; f < 16; ++f) acc[f] += x4.y * wr[16 + f];
#pragma unroll
            for (int f = 0; f < 16; ++f) acc[f] += x4.z * wr[32 + f];
#pragma unroll
            for (int f = 0; f < 16; ++f) acc[f] += x4.w * wr[48 + f];
        }
    }

    float4* dst = reinterpret_cast<float4*>(g_z + ((d * NSEG + s) * BW + w) * FOUT);
#pragma unroll
    for (int fg = 0; fg < 4; ++fg) {
        float4 v;
        v.x = fmaxf(acc[fg * 4 + 0] + bs[fg * 4 + 0], 0.f);
        v.y = fmaxf(acc[fg * 4 + 1] + bs[fg * 4 + 1], 0.f);
        v.z = fmaxf(acc[fg * 4 + 2] + bs[fg * 4 + 2], 0.f);
        v.w = fmaxf(acc[fg * 4 + 3] + bs[fg * 4 + 3], 0.f);
        dst[fg] = v;
    }
}

// ---------------------------------------------------------------------------
// Kernel 3: Y[n,w,:] = sum_d g_z[d, index[d,n], w, :]
// one thread per 16B (4 floats); warp covers one n (512B fully coalesced)
// ---------------------------------------------------------------------------
__global__ void __launch_bounds__(256)
gather_out_kernel(const int* __restrict__ index, float* __restrict__ out)
{
    const int gt = blockIdx.x * 256 + threadIdx.x;   // 0 .. NPTS*BW*4-1
    if (gt >= NPTS * BW * 4) return;
    const int n   = gt >> 5;          // point
    const int rem = gt & 31;          // (w, fg)

    // 3 independent 16B loads (MLP=3), indices broadcast within the warp
    const int s0 = index[n];
    const int s1 = index[NPTS + n];
    const int s2 = index[2 * NPTS + n];

    const float4* b0 = reinterpret_cast<const float4*>(
        g_z + (size_t)s0 * (BW * FOUT)) + rem;
    const float4* b1 = reinterpret_cast<const float4*>(
        g_z + (size_t)(NSEG + s1) * (BW * FOUT)) + rem;
    const float4* b2 = reinterpret_cast<const float4*>(
        g_z + (size_t)(2 * NSEG + s2) * (BW * FOUT)) + rem;

    const float4 v0 = *b0;
    const float4 v1 = *b1;
    const float4 v2 = *b2;

    float4 r;
    r.x = v0.x + v1.x + v2.x;
    r.y = v0.y + v1.y + v2.y;
    r.z = v0.z + v1.z + v2.z;
    r.w = v0.w + v1.w + v2.w;
    reinterpret_cast<float4*>(out)[gt] = r;
}

// ---------------------------------------------------------------------------
extern "C" void kernel_launch(void* const* d_in, const int* in_sizes, int n_in,
                              void* d_out, int out_size)
{
    const float* X      = (const float*)d_in[0];
    const int*   inv    = (const int*)  d_in[1];
    const int*   index  = (const int*)  d_in[2];
    const float* pre_w  = (const float*)d_in[3];
    const float* pre_b  = (const float*)d_in[4];
    const float* post_w = (const float*)d_in[5];
    const float* post_b = (const float*)d_in[6];
    float*       out    = (float*)      d_out;

    cudaFuncSetAttribute((const void*)pre_conv_kernel,
                         cudaFuncAttributeMaxDynamicSharedMemorySize, SM_BYTES);

    zero_seg_kernel<<<2048, 256>>>();

    dim3 g1((NPTS + PN - 1) / PN, NDIM);
    pre_conv_kernel<<<g1, T1, SM_BYTES>>>(X, inv, index, pre_w, pre_b);

    dim3 g2(NSEG * BW / 256, NDIM);
    post_conv_kernel<<<g2, 256>>>(post_w, post_b);

    gather_out_kernel<<<(NPTS * BW * 4 + 255) / 256, 256>>>(index, out);
}